// round 15
// baseline (speedup 1.0000x reference)
#include <cuda_runtime.h>
#include <cuda_bf16.h>
#include <cstdint>

#define SEQ    4096
#define HID    512
#define G4     2048          // 4*HID
#define NCD    32            // CTAs per direction in the recurrence
#define NTH    512           // threads per LSTM CTA (16 warps, 1 output each)
#define JH     16            // h outputs per CTA
#define VOC    32000
#define KH     1024          // head GEMM K (2*HID)

// ---------------- scratch (device globals; no allocation allowed) ----------------
static __device__ __align__(16) float    g_x0 [SEQ * HID];
static __device__ __align__(16) float    g_xpf[SEQ * G4];
static __device__ __align__(16) float    g_xpb[SEQ * G4];
static __device__ __align__(16) float    g_h0 [SEQ * 2 * HID];
static __device__ __align__(16) float    g_h1 [SEQ * 2 * HID];
// bf16 hi/lo splits
static __device__ __align__(16) __nv_bfloat16 g_whi [VOC * KH];
static __device__ __align__(16) __nv_bfloat16 g_wlo [VOC * KH];
static __device__ __align__(16) __nv_bfloat16 g_ahi [SEQ * KH];
static __device__ __align__(16) __nv_bfloat16 g_alo [SEQ * KH];
static __device__ __align__(16) __nv_bfloat16 g_w0fhi[G4 * HID], g_w0flo[G4 * HID];
static __device__ __align__(16) __nv_bfloat16 g_w0bhi[G4 * HID], g_w0blo[G4 * HID];
static __device__ __align__(16) __nv_bfloat16 g_w1fhi[G4 * KH],  g_w1flo[G4 * KH];
static __device__ __align__(16) __nv_bfloat16 g_w1bhi[G4 * KH],  g_w1blo[G4 * KH];

// ---------------- embed ----------------
__global__ void embed_kernel(const int* __restrict__ idx, const float* __restrict__ ew) {
    int s = blockIdx.x;
    int r = idx[s];
    ((float4*)(g_x0 + (size_t)s * HID))[threadIdx.x] =
        ((const float4*)(ew + (size_t)r * HID))[threadIdx.x];
}

// ---------------- canary fill (NaN) for the data-is-flag h exchange ----------------
__global__ void canary_fill(float* __restrict__ p) {
    const unsigned NANP = 0x7FC00000u;
    uint4 v = make_uint4(NANP, NANP, NANP, NANP);
    ((uint4*)p)[(size_t)blockIdx.x * 256 + threadIdx.x] = v;
}

// ---------------- fp32 -> bf16 hi/lo split ----------------
__global__ void split_bf16(const float* __restrict__ src,
                           __nv_bfloat16* __restrict__ hi, __nv_bfloat16* __restrict__ lo) {
    int i = blockIdx.x * 256 + threadIdx.x;        // one float4 per thread
    float4 v = __ldg((const float4*)src + i);
    __nv_bfloat16 h0 = __float2bfloat16_rn(v.x), h1 = __float2bfloat16_rn(v.y);
    __nv_bfloat16 h2 = __float2bfloat16_rn(v.z), h3 = __float2bfloat16_rn(v.w);
    __nv_bfloat16 l0 = __float2bfloat16_rn(v.x - __bfloat162float(h0));
    __nv_bfloat16 l1 = __float2bfloat16_rn(v.y - __bfloat162float(h1));
    __nv_bfloat16 l2 = __float2bfloat16_rn(v.z - __bfloat162float(h2));
    __nv_bfloat16 l3 = __float2bfloat16_rn(v.w - __bfloat162float(h3));
    ushort4 hv = make_ushort4(*(unsigned short*)&h0, *(unsigned short*)&h1,
                              *(unsigned short*)&h2, *(unsigned short*)&h3);
    ushort4 lv = make_ushort4(*(unsigned short*)&l0, *(unsigned short*)&l1,
                              *(unsigned short*)&l2, *(unsigned short*)&l3);
    ((ushort4*)hi)[i] = hv;
    ((ushort4*)lo)[i] = lv;
}

// ---------------- persistent bidirectional LSTM layer ----------------
// CTA-barrier-coupled NaN-canary poll (R11/R14, the proven-live form) feeding
// warp-per-output in-warp compute: each of the 16 warps owns one hidden output;
// weights in lane registers, butterfly reduce, parallel gate activations,
// redundant per-lane cell state. Two barriers per step (poll + stage).
__device__ __forceinline__ float4 ldcg_f4(const float4* p) {
    float4 v;
    asm volatile("ld.global.cg.v4.f32 {%0,%1,%2,%3}, [%4];"
                 : "=f"(v.x), "=f"(v.y), "=f"(v.z), "=f"(v.w) : "l"(p) : "memory");
    return v;
}

__global__ void __launch_bounds__(NTH, 1) lstm_layer_kernel(
    const float* __restrict__ xpf, const float* __restrict__ xpb,
    const float* __restrict__ Whf, const float* __restrict__ Whb,
    float* __restrict__ hcat)
{
    __shared__ __align__(16) float hsh[HID];

    const int tid  = threadIdx.x;
    const int wid  = tid >> 5;              // 0..15: output index within CTA
    const int lane = tid & 31;
    const int dir  = blockIdx.x >> 5;       // NCD == 32
    const int cid  = blockIdx.x & 31;
    const int hj   = cid * JH + wid;        // global hidden index 0..511
    const float* xp = dir ? xpb : xpf;
    const float* W  = dir ? Whb : Whf;

    // weights: 4 gate rows x 16 k-values per lane; k = 4*lane + 128*m + comp
    float4 wr[4][4];
#pragma unroll
    for (int g = 0; g < 4; g++) {
        const size_t row = (size_t)(g * HID + hj) * HID;
#pragma unroll
        for (int m = 0; m < 4; m++)
            wr[g][m] = __ldg((const float4*)&W[row + 4 * lane + 128 * m]);
    }
    if (tid < 128) ((float4*)hsh)[tid] = make_float4(0.f, 0.f, 0.f, 0.f);
    float creg = 0.f;                        // cell state (redundant in all lanes)
    __syncthreads();

    for (int t = 0; t < SEQ; t++) {
        const int tt = dir ? (SEQ - 1 - t) : t;
        // xproj for this output's 4 gates: lane g<4 loads gate g (includes bias)
        float xval = 0.f;
        if (lane < 4) xval = __ldg(&xp[(size_t)tt * G4 + lane * HID + hj]);

        if (t > 0) {
            const int ttp = dir ? (tt + 1) : (tt - 1);
            const float4* hrow = (const float4*)&hcat[(size_t)ttp * (2 * HID) + dir * HID];
            float4 h4 = make_float4(0.f, 0.f, 0.f, 0.f);
            for (;;) {
                bool ok = true;
                if (tid < 128) {
                    h4 = ldcg_f4(hrow + tid);
                    // canary is NaN; real h is always finite
                    ok = (h4.x == h4.x) && (h4.y == h4.y) && (h4.z == h4.z) && (h4.w == h4.w);
                }
                if (__syncthreads_and(ok)) break;   // also closes the previous step
            }
            if (tid < 128) ((float4*)hsh)[tid] = h4;
            __syncthreads();
        }

        // in-warp matvec: 4 gate partial sums per lane from SMEM h
        float acc[4] = {0.f, 0.f, 0.f, 0.f};
#pragma unroll
        for (int m = 0; m < 4; m++) {
            const float4 h4v = *(const float4*)&hsh[4 * lane + 128 * m];
#pragma unroll
            for (int g = 0; g < 4; g++)
                acc[g] += h4v.x * wr[g][m].x + h4v.y * wr[g][m].y
                        + h4v.z * wr[g][m].z + h4v.w * wr[g][m].w;
        }
        // butterfly reduce: all lanes end with all 4 gate sums
#pragma unroll
        for (int off = 16; off > 0; off >>= 1)
#pragma unroll
            for (int g = 0; g < 4; g++)
                acc[g] += __shfl_xor_sync(0xffffffffu, acc[g], off);

        // gates: lanes 0..3 compute the 4 activations in parallel
        float act = 0.f;
        if (lane < 4) {
            float z = acc[lane] + xval;
            act = (lane == 2) ? (2.f / (1.f + __expf(-2.f * z)) - 1.f)   // g: tanh
                              : (1.f / (1.f + __expf(-z)));               // i,f,o: sigmoid
        }
        const float ig = __shfl_sync(0xffffffffu, act, 0);
        const float fg = __shfl_sync(0xffffffffu, act, 1);
        const float gg = __shfl_sync(0xffffffffu, act, 2);
        const float og = __shfl_sync(0xffffffffu, act, 3);
        creg = fg * creg + ig * gg;
        const float h = og * (2.f / (1.f + __expf(-2.f * creg)) - 1.f);
        if (lane == 0)
            __stcg(&hcat[(size_t)tt * (2 * HID) + dir * HID + hj], h);  // data IS the flag
    }
}

// ---------------- bf16 mma.sync GEMM: out[M,N] = A[M,K]*B[N,K]^T + bias ----------
#define KC    32
#define RS    40                 // padded SMEM row stride (bf16 elems)
#define TSM   (128 * RS)         // bf16 elems per tile

#define MMA16816(c, a, b) \
    asm volatile("mma.sync.aligned.m16n8k16.row.col.f32.bf16.bf16.f32 " \
        "{%0,%1,%2,%3}, {%4,%5,%6,%7}, {%8,%9}, {%0,%1,%2,%3};" \
        : "+f"((c)[0]), "+f"((c)[1]), "+f"((c)[2]), "+f"((c)[3]) \
        : "r"((a)[0]), "r"((a)[1]), "r"((a)[2]), "r"((a)[3]), \
          "r"((b)[0]), "r"((b)[1]))

__global__ void __launch_bounds__(256, 1) mma_gemm(
    const __nv_bfloat16* __restrict__ Ahi, const __nv_bfloat16* __restrict__ Alo,
    const __nv_bfloat16* __restrict__ Bhi, const __nv_bfloat16* __restrict__ Blo,
    const float* __restrict__ bias, float* __restrict__ out,
    int K, int ldout)
{
    extern __shared__ __nv_bfloat16 sm[];   // [2][4][TSM]: Ahi, Alo, Bhi, Blo
    const int tid  = threadIdx.x;
    const int wid  = tid >> 5;
    const int lane = tid & 31;
    const int wm   = (wid >> 1) * 32;
    const int wn   = (wid & 1) * 64;
    const int bm   = blockIdx.x * 128;      // m fastest -> B streams once per wave
    const int bn   = blockIdx.y * 128;
    const int nkc  = K / KC;

    float acc[2][8][4];
#pragma unroll
    for (int i = 0; i < 2; i++)
#pragma unroll
        for (int j = 0; j < 8; j++)
#pragma unroll
            for (int q = 0; q < 4; q++) acc[i][j][q] = 0.f;

    auto stage = [&](int kc, int buf) {
        const int k0 = kc * KC;
        __nv_bfloat16* b = sm + buf * 4 * TSM;
#pragma unroll
        for (int it = 0; it < 2; it++) {
            int idx = tid + it * 256;        // 0..511
            int row = idx >> 2;              // 0..127
            int c4  = idx & 3;
            size_t ga = (size_t)(bm + row) * K + k0 + c4 * 8;
            size_t gb = (size_t)(bn + row) * K + k0 + c4 * 8;
            uint32_t so = row * RS + c4 * 8;
            *(uint4*)(b + 0 * TSM + so) = __ldg((const uint4*)(Ahi + ga));
            *(uint4*)(b + 1 * TSM + so) = __ldg((const uint4*)(Alo + ga));
            *(uint4*)(b + 2 * TSM + so) = __ldg((const uint4*)(Bhi + gb));
            *(uint4*)(b + 3 * TSM + so) = __ldg((const uint4*)(Blo + gb));
        }
    };

    stage(0, 0);
    __syncthreads();

    const int g = lane >> 2;
    const int q = lane & 3;

    for (int kc = 0; kc < nkc; kc++) {
        if (kc + 1 < nkc) stage(kc + 1, (kc + 1) & 1);
        const __nv_bfloat16* buf = sm + (kc & 1) * 4 * TSM;
        const __nv_bfloat16* sAh = buf + 0 * TSM;
        const __nv_bfloat16* sAl = buf + 1 * TSM;
        const __nv_bfloat16* sBh = buf + 2 * TSM;
        const __nv_bfloat16* sBl = buf + 3 * TSM;
#pragma unroll
        for (int ks = 0; ks < 2; ks++) {
            const int kk = ks * 16 + q * 2;
            uint32_t ah[2][4], al[2][4];
#pragma unroll
            for (int mi = 0; mi < 2; mi++) {
                const int r = wm + mi * 16 + g;
                ah[mi][0] = *(const uint32_t*)(sAh + r * RS + kk);
                ah[mi][1] = *(const uint32_t*)(sAh + (r + 8) * RS + kk);
                ah[mi][2] = *(const uint32_t*)(sAh + r * RS + kk + 8);
                ah[mi][3] = *(const uint32_t*)(sAh + (r + 8) * RS + kk + 8);
                al[mi][0] = *(const uint32_t*)(sAl + r * RS + kk);
                al[mi][1] = *(const uint32_t*)(sAl + (r + 8) * RS + kk);
                al[mi][2] = *(const uint32_t*)(sAl + r * RS + kk + 8);
                al[mi][3] = *(const uint32_t*)(sAl + (r + 8) * RS + kk + 8);
            }
#pragma unroll
            for (int ni = 0; ni < 8; ni++) {
                const int n = wn + ni * 8 + g;
                uint32_t bh[2], bl[2];
                bh[0] = *(const uint32_t*)(sBh + n * RS + kk);
                bh[1] = *(const uint32_t*)(sBh + n * RS + kk + 8);
                bl[0] = *(const uint32_t*)(sBl + n * RS + kk);
                bl[1] = *(const uint32_t*)(sBl + n * RS + kk + 8);
#pragma unroll
                for (int mi = 0; mi < 2; mi++) {
                    MMA16816(acc[mi][ni], ah[mi], bh);
                    MMA16816(acc[mi][ni], ah[mi], bl);
                    MMA16816(acc[mi][ni], al[mi], bh);
                }
            }
        }
        __syncthreads();
    }

#pragma unroll
    for (int mi = 0; mi < 2; mi++) {
        const int row0 = bm + wm + mi * 16 + g;
        float* o0 = out + (size_t)row0 * ldout + bn + wn;
        float* o1 = o0 + (size_t)8 * ldout;
#pragma unroll
        for (int ni = 0; ni < 8; ni++) {
            const int c = ni * 8 + q * 2;
            float2 bb = *(const float2*)&bias[bn + wn + c];
            float2 v0, v1;
            v0.x = acc[mi][ni][0] + bb.x;  v0.y = acc[mi][ni][1] + bb.y;
            v1.x = acc[mi][ni][2] + bb.x;  v1.y = acc[mi][ni][3] + bb.y;
            *(float2*)(o0 + c) = v0;
            *(float2*)(o1 + c) = v1;
        }
    }
}

// ---------------- launch ----------------
extern "C" void kernel_launch(void* const* d_in, const int* in_sizes, int n_in,
                              void* d_out, int out_size)
{
    (void)in_sizes; (void)n_in; (void)out_size;
    const int*   idx   = (const int*)  d_in[0];
    const float* ew    = (const float*)d_in[1];
    const float* Wih0f = (const float*)d_in[2];
    const float* Whh0f = (const float*)d_in[3];
    const float* b0f   = (const float*)d_in[4];
    const float* Wih0b = (const float*)d_in[5];
    const float* Whh0b = (const float*)d_in[6];
    const float* b0b   = (const float*)d_in[7];
    const float* Wih1f = (const float*)d_in[8];
    const float* Whh1f = (const float*)d_in[9];
    const float* b1f   = (const float*)d_in[10];
    const float* Wih1b = (const float*)d_in[11];
    const float* Whh1b = (const float*)d_in[12];
    const float* b1b   = (const float*)d_in[13];
    const float* Wlin  = (const float*)d_in[14];
    const float* blin  = (const float*)d_in[15];
    float* out = (float*)d_out;

    float *x0, *xpf, *xpb, *h0, *h1;
    __nv_bfloat16 *whi, *wlo, *ahi, *alo;
    __nv_bfloat16 *w0fh, *w0fl, *w0bh, *w0bl, *w1fh, *w1fl, *w1bh, *w1bl;
    cudaGetSymbolAddress((void**)&x0,  g_x0);
    cudaGetSymbolAddress((void**)&xpf, g_xpf);
    cudaGetSymbolAddress((void**)&xpb, g_xpb);
    cudaGetSymbolAddress((void**)&h0,  g_h0);
    cudaGetSymbolAddress((void**)&h1,  g_h1);
    cudaGetSymbolAddress((void**)&whi, g_whi);
    cudaGetSymbolAddress((void**)&wlo, g_wlo);
    cudaGetSymbolAddress((void**)&ahi, g_ahi);
    cudaGetSymbolAddress((void**)&alo, g_alo);
    cudaGetSymbolAddress((void**)&w0fh, g_w0fhi);  cudaGetSymbolAddress((void**)&w0fl, g_w0flo);
    cudaGetSymbolAddress((void**)&w0bh, g_w0bhi);  cudaGetSymbolAddress((void**)&w0bl, g_w0blo);
    cudaGetSymbolAddress((void**)&w1fh, g_w1fhi);  cudaGetSymbolAddress((void**)&w1fl, g_w1flo);
    cudaGetSymbolAddress((void**)&w1bh, g_w1bhi);  cudaGetSymbolAddress((void**)&w1bl, g_w1blo);

    const int gemm_smem = 2 * 4 * TSM * (int)sizeof(__nv_bfloat16);   // 81920
    cudaFuncSetAttribute(mma_gemm, cudaFuncAttributeMaxDynamicSharedMemorySize, gemm_smem);

    // 0) embed + canary-fill both h buffers (data-is-flag sync)
    embed_kernel<<<SEQ, 128>>>(idx, ew);
    canary_fill<<<SEQ * 2 * HID / 4 / 256, 256>>>(h0);
    canary_fill<<<SEQ * 2 * HID / 4 / 256, 256>>>(h1);
    // 1) weight/activation splits for layer-0 xproj + head weights
    split_bf16<<<(VOC * KH / 4) / 256, 256>>>(Wlin, whi, wlo);
    split_bf16<<<(SEQ * HID / 4) / 256, 256>>>(x0, ahi, alo);
    split_bf16<<<(G4 * HID / 4) / 256, 256>>>(Wih0f, w0fh, w0fl);
    split_bf16<<<(G4 * HID / 4) / 256, 256>>>(Wih0b, w0bh, w0bl);
    // 2) layer-0 xproj (M=SEQ, N=G4, K=HID)
    {
        dim3 grid(SEQ / 128, G4 / 128);      // 32 x 16
        mma_gemm<<<grid, 256, gemm_smem>>>(ahi, alo, w0fh, w0fl, b0f, xpf, HID, G4);
        mma_gemm<<<grid, 256, gemm_smem>>>(ahi, alo, w0bh, w0bl, b0b, xpb, HID, G4);
    }
    // 3) layer-0 recurrence
    lstm_layer_kernel<<<2 * NCD, NTH>>>(xpf, xpb, Whh0f, Whh0b, h0);
    // 4) splits for layer-1 xproj
    split_bf16<<<(SEQ * KH / 4) / 256, 256>>>(h0, ahi, alo);
    split_bf16<<<(G4 * KH / 4) / 256, 256>>>(Wih1f, w1fh, w1fl);
    split_bf16<<<(G4 * KH / 4) / 256, 256>>>(Wih1b, w1bh, w1bl);
    // 5) layer-1 xproj (K=KH)
    {
        dim3 grid(SEQ / 128, G4 / 128);
        mma_gemm<<<grid, 256, gemm_smem>>>(ahi, alo, w1fh, w1fl, b1f, xpf, KH, G4);
        mma_gemm<<<grid, 256, gemm_smem>>>(ahi, alo, w1bh, w1bl, b1b, xpb, KH, G4);
    }
    // 6) layer-1 recurrence
    lstm_layer_kernel<<<2 * NCD, NTH>>>(xpf, xpb, Whh1f, Whh1b, h1);
    // 7) head
    split_bf16<<<(SEQ * KH / 4) / 256, 256>>>(h1, ahi, alo);
    {
        dim3 grid(SEQ / 128, VOC / 128);     // 32 x 250
        mma_gemm<<<grid, 256, gemm_smem>>>(ahi, alo, whi, wlo, blin, out, KH, VOC);
    }
}

// round 16
// speedup vs baseline: 1.1346x; 1.1346x over previous
#include <cuda_runtime.h>
#include <cuda_bf16.h>
#include <cstdint>

#define SEQ    4096
#define HID    512
#define G4     2048          // 4*HID
#define NCD    32            // CTAs per direction in the recurrence
#define NTH    512           // threads per LSTM CTA
#define JH     16            // h outputs per CTA (64 gate rows)
#define VOC    32000
#define KH     1024          // head GEMM K (2*HID)

// ---------------- scratch (device globals; no allocation allowed) ----------------
static __device__ __align__(16) float    g_xpf[SEQ * G4];
static __device__ __align__(16) float    g_xpb[SEQ * G4];
static __device__ __align__(16) float    g_h0 [SEQ * 2 * HID];
static __device__ __align__(16) float    g_h1 [SEQ * 2 * HID];
// bf16 hi/lo splits
static __device__ __align__(16) __nv_bfloat16 g_whi [VOC * KH];
static __device__ __align__(16) __nv_bfloat16 g_wlo [VOC * KH];
static __device__ __align__(16) __nv_bfloat16 g_ahi [SEQ * KH];
static __device__ __align__(16) __nv_bfloat16 g_alo [SEQ * KH];
static __device__ __align__(16) __nv_bfloat16 g_w0fhi[G4 * HID], g_w0flo[G4 * HID];
static __device__ __align__(16) __nv_bfloat16 g_w0bhi[G4 * HID], g_w0blo[G4 * HID];
static __device__ __align__(16) __nv_bfloat16 g_w1fhi[G4 * KH],  g_w1flo[G4 * KH];
static __device__ __align__(16) __nv_bfloat16 g_w1bhi[G4 * KH],  g_w1blo[G4 * KH];

// ---------------- split helpers ----------------
__device__ __forceinline__ void split4(float4 v, ushort4& hv, ushort4& lv) {
    __nv_bfloat16 h0 = __float2bfloat16_rn(v.x), h1 = __float2bfloat16_rn(v.y);
    __nv_bfloat16 h2 = __float2bfloat16_rn(v.z), h3 = __float2bfloat16_rn(v.w);
    __nv_bfloat16 l0 = __float2bfloat16_rn(v.x - __bfloat162float(h0));
    __nv_bfloat16 l1 = __float2bfloat16_rn(v.y - __bfloat162float(h1));
    __nv_bfloat16 l2 = __float2bfloat16_rn(v.z - __bfloat162float(h2));
    __nv_bfloat16 l3 = __float2bfloat16_rn(v.w - __bfloat162float(h3));
    hv = make_ushort4(*(unsigned short*)&h0, *(unsigned short*)&h1,
                      *(unsigned short*)&h2, *(unsigned short*)&h3);
    lv = make_ushort4(*(unsigned short*)&l0, *(unsigned short*)&l1,
                      *(unsigned short*)&l2, *(unsigned short*)&l3);
}

// ---------------- embed + direct bf16 split of x0 ----------------
__global__ void embed_kernel(const int* __restrict__ idx, const float* __restrict__ ew) {
    int s = blockIdx.x;               // 4096 blocks, 128 threads (4 floats each)
    int r = idx[s];
    float4 v = ((const float4*)(ew + (size_t)r * HID))[threadIdx.x];
    ushort4 hv, lv;
    split4(v, hv, lv);
    ((ushort4*)(g_ahi + (size_t)s * HID))[threadIdx.x] = hv;
    ((ushort4*)(g_alo + (size_t)s * HID))[threadIdx.x] = lv;
}

// ---------------- canary fill (NaN) for the data-is-flag h exchange ----------------
__global__ void canary_fill(float* __restrict__ p) {
    const unsigned NANP = 0x7FC00000u;
    uint4 v = make_uint4(NANP, NANP, NANP, NANP);
    ((uint4*)p)[(size_t)blockIdx.x * 256 + threadIdx.x] = v;
}

// ---------------- fp32 -> bf16 hi/lo split (single / fused-pair) ----------------
__global__ void split_bf16(const float* __restrict__ src,
                           __nv_bfloat16* __restrict__ hi, __nv_bfloat16* __restrict__ lo) {
    int i = blockIdx.x * 256 + threadIdx.x;
    ushort4 hv, lv;
    split4(__ldg((const float4*)src + i), hv, lv);
    ((ushort4*)hi)[i] = hv;
    ((ushort4*)lo)[i] = lv;
}
__global__ void split2_bf16(const float* __restrict__ srcA,
                            __nv_bfloat16* __restrict__ hiA, __nv_bfloat16* __restrict__ loA,
                            const float* __restrict__ srcB,
                            __nv_bfloat16* __restrict__ hiB, __nv_bfloat16* __restrict__ loB) {
    int i = blockIdx.x * 256 + threadIdx.x;
    ushort4 hv, lv;
    split4(__ldg((const float4*)srcA + i), hv, lv);
    ((ushort4*)hiA)[i] = hv;  ((ushort4*)loA)[i] = lv;
    split4(__ldg((const float4*)srcB + i), hv, lv);
    ((ushort4*)hiB)[i] = hv;  ((ushort4*)loB)[i] = lv;
}

// ---------------- persistent bidirectional LSTM layer (R14 + stage-in-poll) -------
// CTA-barrier-coupled NaN-canary data-is-flag poll (the only weak-poll form
// proven live on this part). Pollers stage hsh inside the loop; the successful
// __syncthreads_and orders the stores. Parallel 64-thread gate epilogue (R14).
// Also emits the bf16 hi/lo split of h (feeds next GEMM without a split pass).
__device__ __forceinline__ float4 ldcg_f4(const float4* p) {
    float4 v;
    asm volatile("ld.global.cg.v4.f32 {%0,%1,%2,%3}, [%4];"
                 : "=f"(v.x), "=f"(v.y), "=f"(v.z), "=f"(v.w) : "l"(p) : "memory");
    return v;
}

__global__ void __launch_bounds__(NTH, 1) lstm_layer_kernel(
    const float* __restrict__ xpf, const float* __restrict__ xpb,
    const float* __restrict__ Whf, const float* __restrict__ Whb,
    float* __restrict__ hcat,
    __nv_bfloat16* __restrict__ hhi, __nv_bfloat16* __restrict__ hlo)
{
    __shared__ __align__(16) float hsh[HID];
    __shared__ float xps[4 * JH];          // 64
    __shared__ float pre[4 * JH];          // 64
    __shared__ float gact[4 * JH];         // 64 parallel gate activations
    __shared__ float csh[JH];

    const int tid = threadIdx.x;
    const int dir = blockIdx.x >> 5;
    const int cid = blockIdx.x & 31;
    const float* xp = dir ? xpb : xpf;
    const float* W  = dir ? Whb : Whf;

    const int rp   = tid >> 4;
    const int ks   = tid & 15;
    const int row0 = rp * 2, row1 = rp * 2 + 1;

    float w0r[32], w1r[32];
    {
        const int g0 = row0 >> 4, j0 = row0 & 15;
        const int g1 = row1 >> 4, j1 = row1 & 15;
        const size_t gr0 = (size_t)(g0 * HID + cid * JH + j0) * HID;
        const size_t gr1 = (size_t)(g1 * HID + cid * JH + j1) * HID;
#pragma unroll
        for (int m = 0; m < 8; m++) {
            const int k = ks * 4 + m * 64;
            float4 v0 = __ldg((const float4*)&W[gr0 + k]);
            float4 v1 = __ldg((const float4*)&W[gr1 + k]);
            w0r[4 * m + 0] = v0.x;  w0r[4 * m + 1] = v0.y;
            w0r[4 * m + 2] = v0.z;  w0r[4 * m + 3] = v0.w;
            w1r[4 * m + 0] = v1.x;  w1r[4 * m + 1] = v1.y;
            w1r[4 * m + 2] = v1.z;  w1r[4 * m + 3] = v1.w;
        }
    }
    if (tid < 128) ((float4*)hsh)[tid] = make_float4(0.f, 0.f, 0.f, 0.f);
    if (tid < JH) csh[tid] = 0.f;
    __syncthreads();

    for (int t = 0; t < SEQ; t++) {
        const int tt = dir ? (SEQ - 1 - t) : t;
        // prefetch this step's xproj values (immutable; includes bias)
        float xval = 0.f;
        if (tid < 4 * JH) {
            int g = tid >> 4, j = tid & 15;
            xval = __ldg(&xp[(size_t)tt * G4 + g * HID + cid * JH + j]);
        }
        if (t > 0) {
            const int ttp = dir ? (tt + 1) : (tt - 1);
            const float4* hrow = (const float4*)&hcat[(size_t)ttp * (2 * HID) + dir * HID];
            for (;;) {
                bool ok = true;
                if (tid < 128) {
                    float4 h4 = ldcg_f4(hrow + tid);
                    // canary is NaN; real h is always finite
                    ok = (h4.x == h4.x) && (h4.y == h4.y) && (h4.z == h4.z) && (h4.w == h4.w);
                    ((float4*)hsh)[tid] = h4;        // stage inside the loop
                }
                if (__syncthreads_and(ok)) break;    // orders the staging stores
            }
        }
        // matvec: pre[r] = sum_k h[k] * Whh[r][k], 2 rows per thread, strided k
        float a0 = 0.f, a1 = 0.f;
#pragma unroll
        for (int m = 0; m < 8; m++) {
            int k = ks * 4 + m * 64;
            float4 h4 = *(const float4*)&hsh[k];
            a0 += h4.x * w0r[4 * m] + h4.y * w0r[4 * m + 1]
                + h4.z * w0r[4 * m + 2] + h4.w * w0r[4 * m + 3];
            a1 += h4.x * w1r[4 * m] + h4.y * w1r[4 * m + 1]
                + h4.z * w1r[4 * m + 2] + h4.w * w1r[4 * m + 3];
        }
#pragma unroll
        for (int off = 8; off > 0; off >>= 1) {
            a0 += __shfl_down_sync(0xffffffffu, a0, off, 16);
            a1 += __shfl_down_sync(0xffffffffu, a1, off, 16);
        }
        if (ks == 0) { pre[row0] = a0; pre[row1] = a1; }
        if (tid < 4 * JH) xps[tid] = xval;
        __syncthreads();

        // parallel gate activations: one thread per gate row (64 total)
        if (tid < 4 * JH) {
            float z = xps[tid] + pre[tid];
            gact[tid] = ((tid >> 4) == 2)
                      ? (2.f / (1.f + __expf(-2.f * z)) - 1.f)   // g gate: tanh
                      : (1.f / (1.f + __expf(-z)));               // i,f,o: sigmoid
        }
        __syncthreads();

        if (tid < JH) {
            const int j = tid;
            float ig = gact[j];
            float fg = gact[JH + j];
            float gg = gact[2 * JH + j];
            float og = gact[3 * JH + j];
            float c  = fg * csh[j] + ig * gg;
            csh[j] = c;
            float h = og * (2.f / (1.f + __expf(-2.f * c)) - 1.f);
            const int hj = cid * JH + j;
            const size_t oidx = (size_t)tt * (2 * HID) + dir * HID + hj;
            __stcg(&hcat[oidx], h);                               // data IS the flag
            // bf16 hi/lo split of h for the next GEMM (no separate split pass)
            __nv_bfloat16 hh = __float2bfloat16_rn(h);
            __nv_bfloat16 hl = __float2bfloat16_rn(h - __bfloat162float(hh));
            hhi[oidx] = hh;
            hlo[oidx] = hl;
        }
        __syncthreads();
    }
}

// ---------------- bf16 mma.sync GEMM: out[M,N] = A[M,K]*B[N,K]^T + bias ----------
#define KC    32
#define RS    40                 // padded SMEM row stride (bf16 elems)
#define TSM   (128 * RS)         // bf16 elems per tile

#define MMA16816(c, a, b) \
    asm volatile("mma.sync.aligned.m16n8k16.row.col.f32.bf16.bf16.f32 " \
        "{%0,%1,%2,%3}, {%4,%5,%6,%7}, {%8,%9}, {%0,%1,%2,%3};" \
        : "+f"((c)[0]), "+f"((c)[1]), "+f"((c)[2]), "+f"((c)[3]) \
        : "r"((a)[0]), "r"((a)[1]), "r"((a)[2]), "r"((a)[3]), \
          "r"((b)[0]), "r"((b)[1]))

__global__ void __launch_bounds__(256, 1) mma_gemm(
    const __nv_bfloat16* __restrict__ Ahi, const __nv_bfloat16* __restrict__ Alo,
    const __nv_bfloat16* __restrict__ Bhi, const __nv_bfloat16* __restrict__ Blo,
    const float* __restrict__ bias, float* __restrict__ out,
    int K, int ldout)
{
    extern __shared__ __nv_bfloat16 sm[];   // [2][4][TSM]: Ahi, Alo, Bhi, Blo
    const int tid  = threadIdx.x;
    const int wid  = tid >> 5;
    const int lane = tid & 31;
    const int wm   = (wid >> 1) * 32;
    const int wn   = (wid & 1) * 64;
    const int bm   = blockIdx.x * 128;      // m fastest -> B streams once per wave
    const int bn   = blockIdx.y * 128;
    const int nkc  = K / KC;

    float acc[2][8][4];
#pragma unroll
    for (int i = 0; i < 2; i++)
#pragma unroll
        for (int j = 0; j < 8; j++)
#pragma unroll
            for (int q = 0; q < 4; q++) acc[i][j][q] = 0.f;

    auto stage = [&](int kc, int buf) {
        const int k0 = kc * KC;
        __nv_bfloat16* b = sm + buf * 4 * TSM;
#pragma unroll
        for (int it = 0; it < 2; it++) {
            int idx = tid + it * 256;        // 0..511
            int row = idx >> 2;              // 0..127
            int c4  = idx & 3;
            size_t ga = (size_t)(bm + row) * K + k0 + c4 * 8;
            size_t gb = (size_t)(bn + row) * K + k0 + c4 * 8;
            uint32_t so = row * RS + c4 * 8;
            *(uint4*)(b + 0 * TSM + so) = __ldg((const uint4*)(Ahi + ga));
            *(uint4*)(b + 1 * TSM + so) = __ldg((const uint4*)(Alo + ga));
            *(uint4*)(b + 2 * TSM + so) = __ldg((const uint4*)(Bhi + gb));
            *(uint4*)(b + 3 * TSM + so) = __ldg((const uint4*)(Blo + gb));
        }
    };

    stage(0, 0);
    __syncthreads();

    const int g = lane >> 2;
    const int q = lane & 3;

    for (int kc = 0; kc < nkc; kc++) {
        if (kc + 1 < nkc) stage(kc + 1, (kc + 1) & 1);
        const __nv_bfloat16* buf = sm + (kc & 1) * 4 * TSM;
        const __nv_bfloat16* sAh = buf + 0 * TSM;
        const __nv_bfloat16* sAl = buf + 1 * TSM;
        const __nv_bfloat16* sBh = buf + 2 * TSM;
        const __nv_bfloat16* sBl = buf + 3 * TSM;
#pragma unroll
        for (int ks = 0; ks < 2; ks++) {
            const int kk = ks * 16 + q * 2;
            uint32_t ah[2][4], al[2][4];
#pragma unroll
            for (int mi = 0; mi < 2; mi++) {
                const int r = wm + mi * 16 + g;
                ah[mi][0] = *(const uint32_t*)(sAh + r * RS + kk);
                ah[mi][1] = *(const uint32_t*)(sAh + (r + 8) * RS + kk);
                ah[mi][2] = *(const uint32_t*)(sAh + r * RS + kk + 8);
                ah[mi][3] = *(const uint32_t*)(sAh + (r + 8) * RS + kk + 8);
                al[mi][0] = *(const uint32_t*)(sAl + r * RS + kk);
                al[mi][1] = *(const uint32_t*)(sAl + (r + 8) * RS + kk);
                al[mi][2] = *(const uint32_t*)(sAl + r * RS + kk + 8);
                al[mi][3] = *(const uint32_t*)(sAl + (r + 8) * RS + kk + 8);
            }
#pragma unroll
            for (int ni = 0; ni < 8; ni++) {
                const int n = wn + ni * 8 + g;
                uint32_t bh[2], bl[2];
                bh[0] = *(const uint32_t*)(sBh + n * RS + kk);
                bh[1] = *(const uint32_t*)(sBh + n * RS + kk + 8);
                bl[0] = *(const uint32_t*)(sBl + n * RS + kk);
                bl[1] = *(const uint32_t*)(sBl + n * RS + kk + 8);
#pragma unroll
                for (int mi = 0; mi < 2; mi++) {
                    MMA16816(acc[mi][ni], ah[mi], bh);
                    MMA16816(acc[mi][ni], ah[mi], bl);
                    MMA16816(acc[mi][ni], al[mi], bh);
                }
            }
        }
        __syncthreads();
    }

#pragma unroll
    for (int mi = 0; mi < 2; mi++) {
        const int row0 = bm + wm + mi * 16 + g;
        float* o0 = out + (size_t)row0 * ldout + bn + wn;
        float* o1 = o0 + (size_t)8 * ldout;
#pragma unroll
        for (int ni = 0; ni < 8; ni++) {
            const int c = ni * 8 + q * 2;
            float2 bb = *(const float2*)&bias[bn + wn + c];
            float2 v0, v1;
            v0.x = acc[mi][ni][0] + bb.x;  v0.y = acc[mi][ni][1] + bb.y;
            v1.x = acc[mi][ni][2] + bb.x;  v1.y = acc[mi][ni][3] + bb.y;
            *(float2*)(o0 + c) = v0;
            *(float2*)(o1 + c) = v1;
        }
    }
}

// ---------------- launch ----------------
extern "C" void kernel_launch(void* const* d_in, const int* in_sizes, int n_in,
                              void* d_out, int out_size)
{
    (void)in_sizes; (void)n_in; (void)out_size;
    const int*   idx   = (const int*)  d_in[0];
    const float* ew    = (const float*)d_in[1];
    const float* Wih0f = (const float*)d_in[2];
    const float* Whh0f = (const float*)d_in[3];
    const float* b0f   = (const float*)d_in[4];
    const float* Wih0b = (const float*)d_in[5];
    const float* Whh0b = (const float*)d_in[6];
    const float* b0b   = (const float*)d_in[7];
    const float* Wih1f = (const float*)d_in[8];
    const float* Whh1f = (const float*)d_in[9];
    const float* b1f   = (const float*)d_in[10];
    const float* Wih1b = (const float*)d_in[11];
    const float* Whh1b = (const float*)d_in[12];
    const float* b1b   = (const float*)d_in[13];
    const float* Wlin  = (const float*)d_in[14];
    const float* blin  = (const float*)d_in[15];
    float* out = (float*)d_out;

    float *xpf, *xpb, *h0, *h1;
    __nv_bfloat16 *whi, *wlo, *ahi, *alo;
    __nv_bfloat16 *w0fh, *w0fl, *w0bh, *w0bl, *w1fh, *w1fl, *w1bh, *w1bl;
    cudaGetSymbolAddress((void**)&xpf, g_xpf);
    cudaGetSymbolAddress((void**)&xpb, g_xpb);
    cudaGetSymbolAddress((void**)&h0,  g_h0);
    cudaGetSymbolAddress((void**)&h1,  g_h1);
    cudaGetSymbolAddress((void**)&whi, g_whi);
    cudaGetSymbolAddress((void**)&wlo, g_wlo);
    cudaGetSymbolAddress((void**)&ahi, g_ahi);
    cudaGetSymbolAddress((void**)&alo, g_alo);
    cudaGetSymbolAddress((void**)&w0fh, g_w0fhi);  cudaGetSymbolAddress((void**)&w0fl, g_w0flo);
    cudaGetSymbolAddress((void**)&w0bh, g_w0bhi);  cudaGetSymbolAddress((void**)&w0bl, g_w0blo);
    cudaGetSymbolAddress((void**)&w1fh, g_w1fhi);  cudaGetSymbolAddress((void**)&w1fl, g_w1flo);
    cudaGetSymbolAddress((void**)&w1bh, g_w1bhi);  cudaGetSymbolAddress((void**)&w1bl, g_w1blo);

    const int gemm_smem = 2 * 4 * TSM * (int)sizeof(__nv_bfloat16);   // 81920
    cudaFuncSetAttribute(mma_gemm, cudaFuncAttributeMaxDynamicSharedMemorySize, gemm_smem);

    // #0 embed (+ x0 bf16 split written directly)
    embed_kernel<<<SEQ, 128>>>(idx, ew);
    // #1 canary h0 (data-is-flag sync)
    canary_fill<<<SEQ * 2 * HID / 4 / 256, 256>>>(h0);
    // #2 layer-0 weight splits (fused pair)
    split2_bf16<<<(G4 * HID / 4) / 256, 256>>>(Wih0f, w0fh, w0fl, Wih0b, w0bh, w0bl);
    // #3,#4 layer-0 xproj (M=SEQ, N=G4, K=HID)
    {
        dim3 grid(SEQ / 128, G4 / 128);      // 32 x 16
        mma_gemm<<<grid, 256, gemm_smem>>>(ahi, alo, w0fh, w0fl, b0f, xpf, HID, G4);
        mma_gemm<<<grid, 256, gemm_smem>>>(ahi, alo, w0bh, w0bl, b0b, xpb, HID, G4);
    }
    // #5 layer-0 recurrence  <-- ncu -s 5 -c 1 lands HERE
    lstm_layer_kernel<<<2 * NCD, NTH>>>(xpf, xpb, Whh0f, Whh0b, h0, ahi, alo);
    // #6 layer-1 weight splits (fused pair)
    split2_bf16<<<(G4 * KH / 4) / 256, 256>>>(Wih1f, w1fh, w1fl, Wih1b, w1bh, w1bl);
    // #7 head weight split
    split_bf16<<<(VOC * KH / 4) / 256, 256>>>(Wlin, whi, wlo);
    // #8 canary h1
    canary_fill<<<SEQ * 2 * HID / 4 / 256, 256>>>(h1);
    // #9,#10 layer-1 xproj (K=KH; A = h0 split emitted by lstm0)
    {
        dim3 grid(SEQ / 128, G4 / 128);
        mma_gemm<<<grid, 256, gemm_smem>>>(ahi, alo, w1fh, w1fl, b1f, xpf, KH, G4);
        mma_gemm<<<grid, 256, gemm_smem>>>(ahi, alo, w1bh, w1bl, b1b, xpb, KH, G4);
    }
    // #11 layer-1 recurrence (emits h1 split into ahi/alo)
    lstm_layer_kernel<<<2 * NCD, NTH>>>(xpf, xpb, Whh1f, Whh1b, h1, ahi, alo);
    // #12 head
    {
        dim3 grid(SEQ / 128, VOC / 128);     // 32 x 250
        mma_gemm<<<grid, 256, gemm_smem>>>(ahi, alo, whi, wlo, blin, out, KH, VOC);
    }
}